// round 4
// baseline (speedup 1.0000x reference)
#include <cuda_runtime.h>
#include <cuda_bf16.h>
#include <cstdint>
#include <cstddef>

#define BB 8
#define SS 4096
#define DD 256
#define CC 64
#define NCHUNK 64
#define NBC (BB * NCHUNK)   // 512

// Scratch
__device__ float         g_S [(size_t)NBC * DD * DD];   // per-chunk S, [bc][i][j]
__device__ __nv_bfloat16 g_Hh[(size_t)NBC * DD * DD];   // incoming state hi
__device__ __nv_bfloat16 g_Hl[(size_t)NBC * DD * DD];   // incoming state lo
__device__ float g_Lg[NBC * CC];
__device__ float g_Gamma[NBC];

// ---------------------------------------------------------------------------
// Helpers
// ---------------------------------------------------------------------------
__device__ __forceinline__ uint32_t smem_u32(const void* p) {
    uint32_t a;
    asm("{ .reg .u64 t; cvta.to.shared.u64 t, %1; cvt.u32.u64 %0, t; }"
        : "=r"(a) : "l"(p));
    return a;
}

__device__ __forceinline__ void mma16816(float c[4], const uint32_t a[4],
                                         const uint32_t b[2]) {
    asm volatile(
        "mma.sync.aligned.m16n8k16.row.col.f32.bf16.bf16.f32 "
        "{%0,%1,%2,%3}, {%4,%5,%6,%7}, {%8,%9}, {%0,%1,%2,%3};"
        : "+f"(c[0]), "+f"(c[1]), "+f"(c[2]), "+f"(c[3])
        : "r"(a[0]), "r"(a[1]), "r"(a[2]), "r"(a[3]), "r"(b[0]), "r"(b[1]));
}

__device__ __forceinline__ void ldmx4(uint32_t r[4], uint32_t a) {
    asm volatile("ldmatrix.sync.aligned.m8n8.x4.shared.b16 {%0,%1,%2,%3}, [%4];"
                 : "=r"(r[0]), "=r"(r[1]), "=r"(r[2]), "=r"(r[3]) : "r"(a));
}
__device__ __forceinline__ void ldmx4t(uint32_t r[4], uint32_t a) {
    asm volatile("ldmatrix.sync.aligned.m8n8.x4.trans.shared.b16 {%0,%1,%2,%3}, [%4];"
                 : "=r"(r[0]), "=r"(r[1]), "=r"(r[2]), "=r"(r[3]) : "r"(a));
}

__device__ __forceinline__ void split4(float4 v, uint2& hi, uint2& lo) {
    float x[4] = { v.x, v.y, v.z, v.w };
    uint32_t h[4], l[4];
    #pragma unroll
    for (int u = 0; u < 4; u++) {
        __nv_bfloat16 hb = __float2bfloat16(x[u]);
        float rres = x[u] - __bfloat162float(hb);
        __nv_bfloat16 lb = __float2bfloat16(rres);
        h[u] = (uint32_t)__bfloat16_as_ushort(hb);
        l[u] = (uint32_t)__bfloat16_as_ushort(lb);
    }
    hi.x = h[0] | (h[1] << 16); hi.y = h[2] | (h[3] << 16);
    lo.x = l[0] | (l[1] << 16); lo.y = l[2] | (l[3] << 16);
}

__device__ __forceinline__ uint32_t pack_bf16x2(float x, float y) {
    __nv_bfloat16 a = __float2bfloat16(x), b = __float2bfloat16(y);
    return (uint32_t)__bfloat16_as_ushort(a) |
           ((uint32_t)__bfloat16_as_ushort(b) << 16);
}

// smem strides (bf16 elems), all ≡ 8 (mod 16) to break conflicts
#define SK 264   // rows of 256
#define SV 136   // rows of 128
#define SAS 72   // rows of 64

// ---------------------------------------------------------------------------
// Kernel A: S quadrant [128 i][128 j] per CTA; grid (NBC, 4).
// ---------------------------------------------------------------------------
#define S_WV   0
#define S_LG   256
#define S_KH   512
#define S_KL   (S_KH + 64 * SV * 2)
#define S_VH   (S_KL + 64 * SV * 2)
#define S_VL   (S_VH + 64 * SV * 2)
#define S_SMEM (S_VL + 64 * SV * 2)   // 70144

__global__ __launch_bounds__(256) void dr_state(
    const float* __restrict__ K, const float* __restrict__ V,
    const float* __restrict__ beta)
{
    extern __shared__ char sm[];
    float* wv  = (float*)(sm + S_WV);
    float* sLg = (float*)(sm + S_LG);
    const int bc = blockIdx.x;
    const int qi = blockIdx.y >> 1, qj = blockIdx.y & 1;
    const int b = bc >> 6, c = bc & 63;
    const int tid = threadIdx.x, wid = tid >> 5, lane = tid & 31;

    if (tid < CC) sLg[tid] = __logf(fmaxf(beta[b * SS + c * CC + tid], 1e-30f));
    __syncthreads();
    if (tid == 0) {
        float s = 0.f;
        #pragma unroll
        for (int u = 0; u < CC; u++) { s += sLg[u]; sLg[u] = s; }
    }
    __syncthreads();
    const float LgEnd = sLg[CC - 1];
    if (tid < CC) {
        wv[tid] = __expf(LgEnd - sLg[tid]);
        if (blockIdx.y == 0) g_Lg[bc * CC + tid] = sLg[tid];
    }
    if (blockIdx.y == 0 && tid == 0) g_Gamma[bc] = __expf(LgEnd);
    __syncthreads();

    __nv_bfloat16* KH = (__nv_bfloat16*)(sm + S_KH);
    __nv_bfloat16* KL = (__nv_bfloat16*)(sm + S_KL);
    __nv_bfloat16* VH = (__nv_bfloat16*)(sm + S_VH);
    __nv_bfloat16* VL = (__nv_bfloat16*)(sm + S_VL);

    const float* Kg = K + ((size_t)b * SS + (size_t)c * CC) * DD + qi * 128;
    const float* Vg = V + ((size_t)b * SS + (size_t)c * CC) * DD + qj * 128;

    #pragma unroll
    for (int it = 0; it < 8; it++) {
        int idx = it * 256 + tid;                 // 0..2047
        int tau = idx >> 5, c4 = (idx & 31) << 2;
        float4 kq = *(const float4*)(Kg + (size_t)tau * DD + c4);
        float wt = wv[tau];
        float4 sc = { kq.x * wt, kq.y * wt, kq.z * wt, kq.w * wt };
        uint2 h, l; split4(sc, h, l);
        *(uint2*)(KH + tau * SV + c4) = h;
        *(uint2*)(KL + tau * SV + c4) = l;
        float4 vq = *(const float4*)(Vg + (size_t)tau * DD + c4);
        split4(vq, h, l);
        *(uint2*)(VH + tau * SV + c4) = h;
        *(uint2*)(VL + tau * SV + c4) = l;
    }
    __syncthreads();

    const int mat = lane >> 3, r = lane & 7, g = lane >> 2, q = lane & 3;
    // trans ldmatrix offsets (stored [k][m] / [k][n], stride SV)
    const uint32_t offAt = (uint32_t)((((mat >> 1) * 8 + r) * (SV * 2)) + (mat & 1) * 16);
    const uint32_t offBt = (uint32_t)((((mat & 1) * 8 + r) * (SV * 2)) + (mat >> 1) * 16);
    const uint32_t khb = smem_u32(sm + S_KH), klb = smem_u32(sm + S_KL);
    const uint32_t vhb = smem_u32(sm + S_VH), vlb = smem_u32(sm + S_VL);

    const int wm = wid >> 1, wn = wid & 1;
    const int i0w = wm * 32, j0w = wn * 64;

    float acc[2][8][4];
    #pragma unroll
    for (int mt = 0; mt < 2; mt++)
        #pragma unroll
        for (int nt = 0; nt < 8; nt++)
            #pragma unroll
            for (int u = 0; u < 4; u++) acc[mt][nt][u] = 0.f;

    #pragma unroll
    for (int pass = 0; pass < 3; pass++) {
        uint32_t ab = (pass == 2) ? klb : khb;
        uint32_t bb = (pass == 1) ? vlb : vhb;
        #pragma unroll
        for (int k0 = 0; k0 < 64; k0 += 16) {
            uint32_t af[2][4], bfm[4][4];
            #pragma unroll
            for (int mt = 0; mt < 2; mt++)
                ldmx4t(af[mt], ab + (uint32_t)(k0 * (SV * 2) + (i0w + mt * 16) * 2) + offAt);
            #pragma unroll
            for (int ng = 0; ng < 4; ng++)
                ldmx4t(bfm[ng], bb + (uint32_t)(k0 * (SV * 2) + (j0w + ng * 16) * 2) + offBt);
            #pragma unroll
            for (int mt = 0; mt < 2; mt++)
                #pragma unroll
                for (int nt = 0; nt < 8; nt++)
                    mma16816(acc[mt][nt], af[mt], &bfm[nt >> 1][(nt & 1) * 2]);
        }
    }

    float* Sdst = g_S + (size_t)bc * 65536 + (size_t)(qi * 128) * 256 + qj * 128;
    #pragma unroll
    for (int mt = 0; mt < 2; mt++)
        #pragma unroll
        for (int nt = 0; nt < 8; nt++) {
            int i = i0w + mt * 16 + g;
            int j = j0w + nt * 8 + 2 * q;
            float2 v0 = { acc[mt][nt][0], acc[mt][nt][1] };
            float2 v1 = { acc[mt][nt][2], acc[mt][nt][3] };
            *(float2*)(Sdst + (size_t)i * 256 + j) = v0;
            *(float2*)(Sdst + (size_t)(i + 8) * 256 + j) = v1;
        }
}

// ---------------------------------------------------------------------------
// Kernel B: cross-chunk scan, float4 per thread.
// ---------------------------------------------------------------------------
__global__ __launch_bounds__(256) void dr_scan()
{
    const int b = blockIdx.y;
    const int tid = threadIdx.x;
    const size_t e4 = ((size_t)blockIdx.x * 256 + tid) * 4;   // 0..65532
    __shared__ float gam[NCHUNK];
    if (tid < NCHUNK) gam[tid] = g_Gamma[b * NCHUNK + tid];
    __syncthreads();

    float4 h = { 0.f, 0.f, 0.f, 0.f };
    const size_t base = (size_t)b * NCHUNK * 65536 + e4;
    for (int c = 0; c < NCHUNK; c++) {
        const size_t off = base + (size_t)c * 65536;
        float4 s = *(const float4*)(g_S + off);
        __nv_bfloat16 hx = __float2bfloat16(h.x), hy = __float2bfloat16(h.y);
        __nv_bfloat16 hz = __float2bfloat16(h.z), hw = __float2bfloat16(h.w);
        uint2 hh = { (uint32_t)__bfloat16_as_ushort(hx) |
                     ((uint32_t)__bfloat16_as_ushort(hy) << 16),
                     (uint32_t)__bfloat16_as_ushort(hz) |
                     ((uint32_t)__bfloat16_as_ushort(hw) << 16) };
        uint2 ll = { pack_bf16x2(h.x - __bfloat162float(hx), h.y - __bfloat162float(hy)),
                     pack_bf16x2(h.z - __bfloat162float(hz), h.w - __bfloat162float(hw)) };
        *(uint2*)(g_Hh + off) = hh;
        *(uint2*)(g_Hl + off) = ll;
        float gc = gam[c];
        h.x = gc * h.x + s.x; h.y = gc * h.y + s.y;
        h.z = gc * h.z + s.z; h.w = gc * h.w + s.w;
    }
}

// ---------------------------------------------------------------------------
// Kernel C: fused output. Per (bc, jh):
//   O[:, jh] = g_i * (Q @ H[:, jh]) + (masked-decayed QK^T) @ V[:, jh]
// 512 threads.
// ---------------------------------------------------------------------------
#define O_QHOFF 512
#define O_QLOFF (O_QHOFF + 64 * SK * 2)
#define O_ASH   (O_QLOFF + 64 * SK * 2)    // 68096
#define O_ASL   (O_ASH + 64 * SAS * 2)
#define O_BIG   (O_ASL + 64 * SAS * 2)     // 86528
#define O_KH    O_BIG
#define O_KL    (O_BIG + 64 * SK * 2)
#define O_VH    O_BIG
#define O_VL    (O_VH + 64 * SV * 2)
#define O_HHOFF (O_VL + 64 * SV * 2)       // 121344
#define O_HLOFF (O_HHOFF + 128 * SV * 2)
#define O_SMEM  (O_HLOFF + 128 * SV * 2)   // 190976

__global__ __launch_bounds__(512) void dr_out(
    const float* __restrict__ Q, const float* __restrict__ K,
    const float* __restrict__ V, float* __restrict__ O)
{
    extern __shared__ char sm[];
    float* sLg = (float*)(sm + 0);
    float* sg  = (float*)(sm + 256);
    const int bc = blockIdx.x, jh = blockIdx.y;
    const int b = bc >> 6, c = bc & 63;
    const int tid = threadIdx.x, wid = tid >> 5, lane = tid & 31;

    if (tid < 64) {
        float lg = g_Lg[bc * CC + tid];
        sLg[tid] = lg;
        sg[tid]  = __expf(lg);
    }

    __nv_bfloat16* QH = (__nv_bfloat16*)(sm + O_QHOFF);
    __nv_bfloat16* QL = (__nv_bfloat16*)(sm + O_QLOFF);
    __nv_bfloat16* KH = (__nv_bfloat16*)(sm + O_KH);
    __nv_bfloat16* KL = (__nv_bfloat16*)(sm + O_KL);

    const size_t chbase = ((size_t)b * SS + (size_t)c * CC) * DD;
    #pragma unroll
    for (int it = 0; it < 8; it++) {
        int idx = it * 512 + tid;                 // 0..4095
        int row = idx >> 6, c4 = (idx & 63) << 2;
        float4 qv = *(const float4*)(Q + chbase + (size_t)row * DD + c4);
        uint2 h, l; split4(qv, h, l);
        *(uint2*)(QH + row * SK + c4) = h;
        *(uint2*)(QL + row * SK + c4) = l;
        float4 kv = *(const float4*)(K + chbase + (size_t)row * DD + c4);
        split4(kv, h, l);
        *(uint2*)(KH + row * SK + c4) = h;
        *(uint2*)(KL + row * SK + c4) = l;
    }
    __syncthreads();

    const int mat = lane >> 3, r = lane & 7, g = lane >> 2, q = lane & 3;
    const uint32_t offA  = (uint32_t)((((mat & 1) * 8 + r) * (SK * 2)) + (mat >> 1) * 16);
    const uint32_t offB4 = (uint32_t)((((lane >> 4) * 8 + (lane & 7)) * (SK * 2)) +
                                      ((lane >> 3) & 1) * 16);
    const uint32_t qhb = smem_u32(sm + O_QHOFF), qlb = smem_u32(sm + O_QLOFF);
    const uint32_t khb = smem_u32(sm + O_KH),   klb = smem_u32(sm + O_KL);

    // ---- Phase 1: A_att = mask(QK^T); 16 warps in 16x16 tiles ----
    const int i0 = (wid >> 2) * 16, t0 = (wid & 3) * 16;
    float acc1[2][4];
    #pragma unroll
    for (int nt = 0; nt < 2; nt++)
        #pragma unroll
        for (int u = 0; u < 4; u++) acc1[nt][u] = 0.f;

    #pragma unroll
    for (int pass = 0; pass < 3; pass++) {
        uint32_t ab = (pass == 2) ? qlb : qhb;
        uint32_t bb = (pass == 1) ? klb : khb;
        #pragma unroll
        for (int d0 = 0; d0 < 256; d0 += 16) {
            uint32_t af[4], bf[4];
            ldmx4(af, ab + (uint32_t)(i0 * (SK * 2) + d0 * 2) + offA);
            ldmx4(bf, bb + (uint32_t)(t0 * (SK * 2) + d0 * 2) + offB4);
            #pragma unroll
            for (int nt = 0; nt < 2; nt++)
                mma16816(acc1[nt], af, &bf[nt * 2]);
        }
    }

    __nv_bfloat16* ASH = (__nv_bfloat16*)(sm + O_ASH);
    __nv_bfloat16* ASL = (__nv_bfloat16*)(sm + O_ASL);
    #pragma unroll
    for (int nt = 0; nt < 2; nt++) {
        int ia = i0 + g, ib = ia + 8;
        int t = t0 + nt * 8 + 2 * q;
        float la = sLg[ia], lb = sLg[ib], l0 = sLg[t], l1 = sLg[t + 1];
        float f00 = (t     <= ia) ? __expf(la - l0) : 0.f;
        float f01 = (t + 1 <= ia) ? __expf(la - l1) : 0.f;
        float f10 = (t     <= ib) ? __expf(lb - l0) : 0.f;
        float f11 = (t + 1 <= ib) ? __expf(lb - l1) : 0.f;
        float a0 = acc1[nt][0] * f00, a1 = acc1[nt][1] * f01;
        float a2 = acc1[nt][2] * f10, a3 = acc1[nt][3] * f11;
        __nv_bfloat16 h0 = __float2bfloat16(a0), h1 = __float2bfloat16(a1);
        __nv_bfloat16 h2 = __float2bfloat16(a2), h3 = __float2bfloat16(a3);
        *(uint32_t*)(ASH + ia * SAS + t) =
            (uint32_t)__bfloat16_as_ushort(h0) | ((uint32_t)__bfloat16_as_ushort(h1) << 16);
        *(uint32_t*)(ASH + ib * SAS + t) =
            (uint32_t)__bfloat16_as_ushort(h2) | ((uint32_t)__bfloat16_as_ushort(h3) << 16);
        *(uint32_t*)(ASL + ia * SAS + t) =
            pack_bf16x2(a0 - __bfloat162float(h0), a1 - __bfloat162float(h1));
        *(uint32_t*)(ASL + ib * SAS + t) =
            pack_bf16x2(a2 - __bfloat162float(h2), a3 - __bfloat162float(h3));
    }
    __syncthreads();   // AS published; K region now dead

    // ---- Phase 2 loads: V (j-half) and H panel 0 ----
    __nv_bfloat16* VH = (__nv_bfloat16*)(sm + O_VH);
    __nv_bfloat16* VL = (__nv_bfloat16*)(sm + O_VL);
    __nv_bfloat16* HH = (__nv_bfloat16*)(sm + O_HHOFF);
    __nv_bfloat16* HL = (__nv_bfloat16*)(sm + O_HLOFF);
    const __nv_bfloat16* HgH = g_Hh + (size_t)bc * 65536 + jh * 128;
    const __nv_bfloat16* HgL = g_Hl + (size_t)bc * 65536 + jh * 128;

    #pragma unroll
    for (int it = 0; it < 4; it++) {
        int idx = it * 512 + tid;                 // 0..2047
        int row = idx >> 5, c4 = (idx & 31) << 2;
        float4 vv = *(const float4*)(V + chbase + (size_t)row * DD + jh * 128 + c4);
        uint2 h, l; split4(vv, h, l);
        *(uint2*)(VH + row * SV + c4) = h;
        *(uint2*)(VL + row * SV + c4) = l;
    }
    #pragma unroll
    for (int it = 0; it < 4; it++) {
        int idx = it * 512 + tid;                 // 0..2047
        int row = idx >> 4, u = (idx & 15) * 8;   // row 0..127
        *(uint4*)(HH + row * SV + u) = *(const uint4*)(HgH + (size_t)row * 256 + u);
        *(uint4*)(HL + row * SV + u) = *(const uint4*)(HgL + (size_t)row * 256 + u);
    }
    __syncthreads();

    // warp tiles for output: 16 warps -> [16 i] x [32 j]
    const int j0 = (wid & 3) * 32;
    const uint32_t offAs = (uint32_t)((((mat & 1) * 8 + r) * (SAS * 2)) + (mat >> 1) * 16);
    const uint32_t offBt = (uint32_t)((((mat & 1) * 8 + r) * (SV * 2)) + (mat >> 1) * 16);
    const uint32_t ash = smem_u32(sm + O_ASH), asl = smem_u32(sm + O_ASL);
    const uint32_t vhb = smem_u32(sm + O_VH), vlb = smem_u32(sm + O_VL);
    const uint32_t hhb = smem_u32(sm + O_HHOFF), hlb = smem_u32(sm + O_HLOFF);

    float accAV[4][4], accQ[4][4];
    #pragma unroll
    for (int nt = 0; nt < 4; nt++)
        #pragma unroll
        for (int u = 0; u < 4; u++) { accAV[nt][u] = 0.f; accQ[nt][u] = 0.f; }

    // AV: K-dim 64 over AS x V
    #pragma unroll
    for (int pass = 0; pass < 3; pass++) {
        uint32_t ab = (pass == 2) ? asl : ash;
        uint32_t bb = (pass == 1) ? vlb : vhb;
        #pragma unroll
        for (int k0 = 0; k0 < 64; k0 += 16) {
            uint32_t af[4], bfm[2][4];
            ldmx4(af, ab + (uint32_t)(i0 * (SAS * 2) + k0 * 2) + offAs);
            #pragma unroll
            for (int ng = 0; ng < 2; ng++)
                ldmx4t(bfm[ng], bb + (uint32_t)(k0 * (SV * 2) + (j0 + ng * 16) * 2) + offBt);
            #pragma unroll
            for (int nt = 0; nt < 4; nt++)
                mma16816(accAV[nt], af, &bfm[nt >> 1][(nt & 1) * 2]);
        }
    }

    // QH panel 0 (d = 0..127)
    #pragma unroll
    for (int pass = 0; pass < 3; pass++) {
        uint32_t ab = (pass == 2) ? qlb : qhb;
        uint32_t bb = (pass == 1) ? hlb : hhb;
        #pragma unroll
        for (int d0 = 0; d0 < 128; d0 += 16) {
            uint32_t af[4], bfm[2][4];
            ldmx4(af, ab + (uint32_t)(i0 * (SK * 2) + d0 * 2) + offA);
            #pragma unroll
            for (int ng = 0; ng < 2; ng++)
                ldmx4t(bfm[ng], bb + (uint32_t)(d0 * (SV * 2) + (j0 + ng * 16) * 2) + offBt);
            #pragma unroll
            for (int nt = 0; nt < 4; nt++)
                mma16816(accQ[nt], af, &bfm[nt >> 1][(nt & 1) * 2]);
        }
    }
    __syncthreads();

    // H panel 1 (d = 128..255)
    #pragma unroll
    for (int it = 0; it < 4; it++) {
        int idx = it * 512 + tid;
        int row = idx >> 4, u = (idx & 15) * 8;
        *(uint4*)(HH + row * SV + u) = *(const uint4*)(HgH + (size_t)(128 + row) * 256 + u);
        *(uint4*)(HL + row * SV + u) = *(const uint4*)(HgL + (size_t)(128 + row) * 256 + u);
    }
    __syncthreads();

    #pragma unroll
    for (int pass = 0; pass < 3; pass++) {
        uint32_t ab = (pass == 2) ? qlb : qhb;
        uint32_t bb = (pass == 1) ? hlb : hhb;
        #pragma unroll
        for (int d0 = 0; d0 < 128; d0 += 16) {
            uint32_t af[4], bfm[2][4];
            ldmx4(af, ab + (uint32_t)(i0 * (SK * 2) + (128 + d0) * 2) + offA);
            #pragma unroll
            for (int ng = 0; ng < 2; ng++)
                ldmx4t(bfm[ng], bb + (uint32_t)(d0 * (SV * 2) + (j0 + ng * 16) * 2) + offBt);
            #pragma unroll
            for (int nt = 0; nt < 4; nt++)
                mma16816(accQ[nt], af, &bfm[nt >> 1][(nt & 1) * 2]);
        }
    }

    // ---- epilogue ----
    float* Od = O + chbase + jh * 128;
    #pragma unroll
    for (int nt = 0; nt < 4; nt++) {
        int ia = i0 + g, ib = ia + 8;
        int j = j0 + nt * 8 + 2 * q;
        float sa = sg[ia], sb2 = sg[ib];
        float2 v0 = { sa * accQ[nt][0] + accAV[nt][0],
                      sa * accQ[nt][1] + accAV[nt][1] };
        float2 v1 = { sb2 * accQ[nt][2] + accAV[nt][2],
                      sb2 * accQ[nt][3] + accAV[nt][3] };
        *(float2*)(Od + (size_t)ia * DD + j) = v0;
        *(float2*)(Od + (size_t)ib * DD + j) = v1;
    }
}

// ---------------------------------------------------------------------------
extern "C" void kernel_launch(void* const* d_in, const int* in_sizes, int n_in,
                              void* d_out, int out_size)
{
    const float* q    = (const float*)d_in[0];
    const float* k    = (const float*)d_in[1];
    const float* v    = (const float*)d_in[2];
    const float* beta = (const float*)d_in[3];
    float* out = (float*)d_out;
    (void)in_sizes; (void)n_in; (void)out_size;

    cudaFuncSetAttribute(dr_state, cudaFuncAttributeMaxDynamicSharedMemorySize, S_SMEM);
    cudaFuncSetAttribute(dr_out,   cudaFuncAttributeMaxDynamicSharedMemorySize, O_SMEM);

    dr_state<<<dim3(NBC, 4), 256, S_SMEM>>>(k, v, beta);
    dr_scan<<<dim3(64, BB), 256>>>();
    dr_out<<<dim3(NBC, 2), 512, O_SMEM>>>(q, k, v, out);
}